// round 8
// baseline (speedup 1.0000x reference)
#include <cuda_runtime.h>
#include <cstdint>

// VN_Attention: B=8, C=64, U=3, N=512
// R8:
//  K1: c-tiled projections (4 output channels per CTA) -> x L2 traffic /4.
//      Writes q pre-scaled and k/v LANE-DUPLICATED ((w,w) ull) to scratch.
//  K2: attention, f32x2 lanes packed over the TWO QUERIES (i0,i1) instead of
//      two j's -> essential regs ~22, launch_bounds(256,7) -> single wave
//      (1024 CTAs <= 148*7). 2-CTA cluster over j-halves, DSMEM partials.

#define BB 8
#define CC 64
#define UU 3
#define NN 512
#define SLAB (UU * NN)          // 1536 floats
#define SLAB2 (SLAB / 2)        // 768 ull
#define NSLAB (BB * CC)         // 512
#define TCOUT 4                 // output channels per K1 CTA
#define KVDUP (NN * 12)         // 6144 floats per slab (duplicated rows)
#define KVDUP2 (KVDUP / 2)      // 3072 ull

typedef unsigned long long ull;
typedef unsigned int u32;

__device__ float qg[NSLAB * SLAB];       // 3 MB,  pre-scaled q, [slab][u][n]
__device__ float kvg[NSLAB * KVDUP];     // 12 MB, [slab][j][12] lane-duplicated

__device__ __forceinline__ float ex2_approx(float x) {
    float r; asm("ex2.approx.ftz.f32 %0, %1;" : "=f"(r) : "f"(x)); return r;
}
__device__ __forceinline__ ull pack2(float lo, float hi) {
    ull r; asm("mov.b64 %0, {%1, %2};" : "=l"(r) : "f"(lo), "f"(hi)); return r;
}
__device__ __forceinline__ void unpack2(ull v, float& lo, float& hi) {
    asm("mov.b64 {%0, %1}, %2;" : "=f"(lo), "=f"(hi) : "l"(v));
}
__device__ __forceinline__ ull fma2(ull a, ull b, ull c) {
    ull d; asm("fma.rn.f32x2 %0, %1, %2, %3;" : "=l"(d) : "l"(a), "l"(b), "l"(c)); return d;
}
__device__ __forceinline__ ull mul2(ull a, ull b) {
    ull d; asm("mul.rn.f32x2 %0, %1, %2;" : "=l"(d) : "l"(a), "l"(b)); return d;
}
__device__ __forceinline__ ull add2(ull a, ull b) {
    ull d; asm("add.rn.f32x2 %0, %1, %2;" : "=l"(d) : "l"(a), "l"(b)); return d;
}
__device__ __forceinline__ u32 smem_u32(const void* p) {
    u32 a;
    asm("{ .reg .u64 t; cvta.to.shared.u64 t, %1; cvt.u32.u64 %0, t; }" : "=r"(a) : "l"(p));
    return a;
}

// ------ K1: projections, grid (8*16, 3): (b, ctile) x u-plane -----------
__global__ __launch_bounds__(256, 6)
void vn_proj_kernel(const float* __restrict__ x,
                    const float* __restrict__ Wq,
                    const float* __restrict__ Wk,
                    const float* __restrict__ Wv)
{
    __shared__ ull wqd[TCOUT][CC], wkd[TCOUT][CC], wvd[TCOUT][CC];  // 6 KB dup
    const int tid = threadIdx.x;
    const int bx = blockIdx.x;
    const int b  = bx >> 4;
    const int c0 = (bx & 15) * TCOUT;
    const int u  = blockIdx.y;

    {   // 256 threads load the 4x64 weight tile of each matrix, duplicated.
        const int co = tid >> 6, ci = tid & 63;
        float w = Wq[(c0 + co) * CC + ci]; wqd[co][ci] = pack2(w, w);
        w = Wk[(c0 + co) * CC + ci];       wkd[co][ci] = pack2(w, w);
        w = Wv[(c0 + co) * CC + ci];       wvd[co][ci] = pack2(w, w);
    }
    __syncthreads();

    ull aq[TCOUT], ak[TCOUT], av[TCOUT];
    #pragma unroll
    for (int co = 0; co < TCOUT; ++co) { aq[co] = 0ull; ak[co] = 0ull; av[co] = 0ull; }

    const ull* xp = reinterpret_cast<const ull*>(x)
                  + (size_t)b * CC * SLAB2 + u * 256 + tid;
    #pragma unroll 4
    for (int ci = 0; ci < CC; ++ci) {
        const ull xv = xp[ci * SLAB2];
        #pragma unroll
        for (int co = 0; co < TCOUT; ++co) {
            aq[co] = fma2(xv, wqd[co][ci], aq[co]);
            ak[co] = fma2(xv, wkd[co][ci], ak[co]);
            av[co] = fma2(xv, wvd[co][ci], av[co]);
        }
    }

    const float qs = 0.125f * 1.44269504088896340736f;  // C^-0.5 * log2(e)
    const ull qs2 = pack2(qs, qs);
    const int j0 = 2 * tid, j1 = 2 * tid + 1;           // n positions in u-plane
    #pragma unroll
    for (int co = 0; co < TCOUT; ++co) {
        const int slab = b * CC + c0 + co;
        ull* qgU = reinterpret_cast<ull*>(qg) + (size_t)slab * SLAB2;
        ull* kvU = reinterpret_cast<ull*>(kvg) + (size_t)slab * KVDUP2;
        qgU[u * 256 + tid] = mul2(aq[co], qs2);
        float lo, hi;
        unpack2(ak[co], lo, hi);
        kvU[j0 * 6 + u] = pack2(lo, lo);
        kvU[j1 * 6 + u] = pack2(hi, hi);
        unpack2(av[co], lo, hi);
        kvU[j0 * 6 + 3 + u] = pack2(lo, lo);
        kvU[j1 * 6 + 3 + u] = pack2(hi, hi);
    }
}

// ------ K2: attention, lanes = (query i0, query i1), 2-CTA cluster over j --
__global__ __launch_bounds__(256, 7) __cluster_dims__(2, 1, 1)
void vn_attn_kernel(const float* __restrict__ x,
                    float* __restrict__ out)
{
    __shared__ __align__(16) float kv[KVDUP / 2];   // 12 KB: 256 dup rows
    __shared__ __align__(16) float4 pbuf[NN];       // 8 KB partials

    const int tid = threadIdx.x;
    const int bc = blockIdx.x >> 1;
    u32 z;                                          // j-half == cluster rank
    asm("mov.u32 %0, %%cluster_ctarank;" : "=r"(z));

    // Straight copy of this j-half's duplicated rows (768 float4).
    {
        const float4* src = reinterpret_cast<const float4*>(
            kvg + (size_t)bc * KVDUP + z * (KVDUP / 2));
        float4* dst = reinterpret_cast<float4*>(kv);
        #pragma unroll
        for (int t = 0; t < 3; ++t)
            dst[tid + t * 256] = src[tid + t * 256];
    }

    // Queries i0 = tid, i1 = tid+256, packed per-lane.
    const float* qb = qg + (size_t)bc * SLAB;
    const int i0 = tid, i1 = tid + 256;
    const ull qA = pack2(qb[0 * NN + i0], qb[0 * NN + i1]);
    const ull qB = pack2(qb[1 * NN + i0], qb[1 * NN + i1]);
    const ull qC = pack2(qb[2 * NN + i0], qb[2 * NN + i1]);
    __syncthreads();

    ull s = 0ull, a0 = 0ull, a1 = 0ull, a2 = 0ull;

    const ulonglong2* kvrow = reinterpret_cast<const ulonglong2*>(kv);
    #pragma unroll 4
    for (int j = 0; j < 256; ++j) {
        const ulonglong2 A = kvrow[j * 3 + 0];   // (k0,k0),(k1,k1)
        const ulonglong2 B = kvrow[j * 3 + 1];   // (k2,k2),(v0,v0)
        const ulonglong2 C = kvrow[j * 3 + 2];   // (v1,v1),(v2,v2)

        ull d = fma2(qA, A.x, fma2(qB, A.y, mul2(qC, B.x)));
        float dl, dh;
        unpack2(d, dl, dh);
        const ull e = pack2(ex2_approx(dl), ex2_approx(dh));

        s  = add2(s, e);
        a0 = fma2(e, B.y, a0);
        a1 = fma2(e, C.x, a1);
        a2 = fma2(e, C.y, a2);
    }

    // Lanes are queries: scatter partials directly.
    float sl, sh, a0l, a0h, a1l, a1h, a2l, a2h;
    unpack2(s,  sl,  sh);
    unpack2(a0, a0l, a0h);
    unpack2(a1, a1l, a1h);
    unpack2(a2, a2l, a2h);
    pbuf[i0] = make_float4(sl, a0l, a1l, a2l);
    pbuf[i1] = make_float4(sh, a0h, a1h, a2h);

    // Cluster barrier: partials visible to peer.
    asm volatile("barrier.cluster.arrive.aligned;" ::: "memory");
    asm volatile("barrier.cluster.wait.aligned;" ::: "memory");

    // Epilogue: finalize queries [z*256, z*256+256).
    const int jq = (int)z * 256 + tid;
    const float4 mine = pbuf[jq];
    float4 theirs;
    {
        u32 laddr = smem_u32(&pbuf[jq]);
        u32 raddr;
        asm("mapa.shared::cluster.u32 %0, %1, %2;" : "=r"(raddr) : "r"(laddr), "r"(z ^ 1u));
        asm("ld.shared::cluster.v4.f32 {%0,%1,%2,%3}, [%4];"
            : "=f"(theirs.x), "=f"(theirs.y), "=f"(theirs.z), "=f"(theirs.w)
            : "r"(raddr));
    }

    const float inv = __fdividef(1.f, mine.x + theirs.x);
    const size_t base = (size_t)bc * SLAB;
    out[base + 0 * NN + jq] = x[base + 0 * NN + jq] + (mine.y + theirs.y) * inv;
    out[base + 1 * NN + jq] = x[base + 1 * NN + jq] + (mine.z + theirs.z) * inv;
    out[base + 2 * NN + jq] = x[base + 2 * NN + jq] + (mine.w + theirs.w) * inv;

    // Keep smem alive until peer finished reading.
    asm volatile("barrier.cluster.arrive.aligned;" ::: "memory");
    asm volatile("barrier.cluster.wait.aligned;" ::: "memory");
}

extern "C" void kernel_launch(void* const* d_in, const int* in_sizes, int n_in,
                              void* d_out, int out_size) {
    const float* x  = (const float*)d_in[0];
    const float* Wq = (const float*)d_in[1];
    const float* Wk = (const float*)d_in[2];
    const float* Wv = (const float*)d_in[3];
    float* out = (float*)d_out;

    dim3 grid1(BB * (CC / TCOUT), UU);
    vn_proj_kernel<<<grid1, 256>>>(x, Wq, Wk, Wv);
    vn_attn_kernel<<<NSLAB * 2, 256>>>(x, out);
}

// round 9
// speedup vs baseline: 1.0373x; 1.0373x over previous
#include <cuda_runtime.h>
#include <cstdint>

// VN_Attention: B=8, C=64, U=3, N=512
// R9:
//  kvg scratch is SoA [slab][comp:6][jpair:256] ull so K1 writes are fully
//  coalesced 2KB runs; K2 transposes to interleaved j-pair rows during its
//  global->smem stage (bank conflicts only on the one-time copy).
//  K1: TCOUT=4 c-tiling, grid (8*16, 3): x L2 traffic 196->49MB.
//  K2: proven R7 inner loop (q=2/thread, j-pair f32x2 packs, 0.375 LDS per
//  (q,j)), 2-CTA cluster over j-halves + DSMEM partials, bounds(256,6).

#define BB 8
#define CC 64
#define UU 3
#define NN 512
#define SLAB (UU * NN)          // 1536 floats
#define SLAB2 (SLAB / 2)        // 768 ull
#define NSLAB (BB * CC)         // 512
#define TCOUT 4
#define KVU 1536                // ull per slab in kvg (6 comps * 256 jpairs)

typedef unsigned long long ull;
typedef unsigned int u32;

__device__ float qg[NSLAB * SLAB];          // 3 MB, pre-scaled q, [slab][u][n]
__device__ ull kvg[(size_t)NSLAB * KVU];    // 6 MB, [slab][comp][jpair]

__device__ __forceinline__ float ex2_approx(float x) {
    float r; asm("ex2.approx.ftz.f32 %0, %1;" : "=f"(r) : "f"(x)); return r;
}
__device__ __forceinline__ ull pack2(float lo, float hi) {
    ull r; asm("mov.b64 %0, {%1, %2};" : "=l"(r) : "f"(lo), "f"(hi)); return r;
}
__device__ __forceinline__ void unpack2(ull v, float& lo, float& hi) {
    asm("mov.b64 {%0, %1}, %2;" : "=f"(lo), "=f"(hi) : "l"(v));
}
__device__ __forceinline__ ull fma2(ull a, ull b, ull c) {
    ull d; asm("fma.rn.f32x2 %0, %1, %2, %3;" : "=l"(d) : "l"(a), "l"(b), "l"(c)); return d;
}
__device__ __forceinline__ ull mul2(ull a, ull b) {
    ull d; asm("mul.rn.f32x2 %0, %1, %2;" : "=l"(d) : "l"(a), "l"(b)); return d;
}
__device__ __forceinline__ ull add2(ull a, ull b) {
    ull d; asm("add.rn.f32x2 %0, %1, %2;" : "=l"(d) : "l"(a), "l"(b)); return d;
}
__device__ __forceinline__ u32 smem_u32(const void* p) {
    u32 a;
    asm("{ .reg .u64 t; cvta.to.shared.u64 t, %1; cvt.u32.u64 %0, t; }" : "=r"(a) : "l"(p));
    return a;
}

// ---- K1: projections. grid (8*16, 3) = (b, ctile) x u-plane, 256 thr. ----
__global__ __launch_bounds__(256, 6)
void vn_proj_kernel(const float* __restrict__ x,
                    const float* __restrict__ Wq,
                    const float* __restrict__ Wk,
                    const float* __restrict__ Wv)
{
    __shared__ ull wqd[TCOUT][CC], wkd[TCOUT][CC], wvd[TCOUT][CC];  // 6 KB dup
    const int tid = threadIdx.x;
    const int bx = blockIdx.x;
    const int b  = bx >> 4;
    const int c0 = (bx & 15) * TCOUT;
    const int u  = blockIdx.y;

    {   // 256 threads load the 4x64 weight tiles, lane-duplicated.
        const int co = tid >> 6, ci = tid & 63;
        float w = Wq[(c0 + co) * CC + ci]; wqd[co][ci] = pack2(w, w);
        w = Wk[(c0 + co) * CC + ci];       wkd[co][ci] = pack2(w, w);
        w = Wv[(c0 + co) * CC + ci];       wvd[co][ci] = pack2(w, w);
    }
    __syncthreads();

    ull aq[TCOUT], ak[TCOUT], av[TCOUT];
    #pragma unroll
    for (int co = 0; co < TCOUT; ++co) { aq[co] = 0ull; ak[co] = 0ull; av[co] = 0ull; }

    const ull* xp = reinterpret_cast<const ull*>(x)
                  + (size_t)b * CC * SLAB2 + u * 256 + tid;
    #pragma unroll 4
    for (int ci = 0; ci < CC; ++ci) {
        const ull xv = xp[(size_t)ci * SLAB2];
        #pragma unroll
        for (int co = 0; co < TCOUT; ++co) {
            aq[co] = fma2(xv, wqd[co][ci], aq[co]);
            ak[co] = fma2(xv, wkd[co][ci], ak[co]);
            av[co] = fma2(xv, wvd[co][ci], av[co]);
        }
    }

    const float qs = 0.125f * 1.44269504088896340736f;  // C^-0.5 * log2(e)
    const ull qs2 = pack2(qs, qs);
    #pragma unroll
    for (int co = 0; co < TCOUT; ++co) {
        const int slab = b * CC + c0 + co;
        // q: [slab][u][n], coalesced.
        reinterpret_cast<ull*>(qg)[(size_t)slab * SLAB2 + u * 256 + tid]
            = mul2(aq[co], qs2);
        // kv SoA: comp u = k_u j-pairs, comp 3+u = v_u j-pairs. Coalesced runs.
        kvg[(size_t)slab * KVU + (u)     * 256 + tid] = ak[co];
        kvg[(size_t)slab * KVU + (3 + u) * 256 + tid] = av[co];
    }
}

// ---- K2: attention. q=2/thread, j-pair packs, 2-CTA cluster over j-halves. --
__global__ __launch_bounds__(256, 6) __cluster_dims__(2, 1, 1)
void vn_attn_kernel(const float* __restrict__ x,
                    float* __restrict__ out)
{
    __shared__ __align__(16) ull kv[128 * 6];        // 6 KB: 128 interleaved rows
    __shared__ __align__(16) float4 pbuf[NN];        // 8 KB partials

    const int tid = threadIdx.x;
    const int bc = blockIdx.x >> 1;
    u32 z;                                           // j-half == cluster rank
    asm("mov.u32 %0, %%cluster_ctarank;" : "=r"(z));

    // Stage: global SoA [comp][jpair] -> smem interleaved [jp][comp].
    {
        const ull* src = kvg + (size_t)bc * KVU + z * 128;
        #pragma unroll
        for (int k = 0; k < 3; ++k) {
            const int idx = tid + k * 256;           // 0..767
            const int comp = idx >> 7;               // 0..5
            const int jp   = idx & 127;
            kv[jp * 6 + comp] = src[comp * 256 + jp];
        }
    }

    // Queries i0 = tid, i1 = tid+256 (pre-scaled q from K1).
    const float* qb = qg + (size_t)bc * SLAB;
    const int i0 = tid, i1 = tid + 256;
    const ull q00 = pack2(qb[0 * NN + i0], qb[0 * NN + i0]);
    const ull q01 = pack2(qb[1 * NN + i0], qb[1 * NN + i0]);
    const ull q02 = pack2(qb[2 * NN + i0], qb[2 * NN + i0]);
    const ull q10 = pack2(qb[0 * NN + i1], qb[0 * NN + i1]);
    const ull q11 = pack2(qb[1 * NN + i1], qb[1 * NN + i1]);
    const ull q12 = pack2(qb[2 * NN + i1], qb[2 * NN + i1]);
    __syncthreads();

    ull s0 = 0ull, a00 = 0ull, a01 = 0ull, a02 = 0ull;
    ull s1 = 0ull, a10 = 0ull, a11 = 0ull, a12 = 0ull;

    const ulonglong2* kvrow = reinterpret_cast<const ulonglong2*>(kv);
    #pragma unroll 4
    for (int p = 0; p < 128; ++p) {
        const ulonglong2 A = kvrow[p * 3 + 0];   // (k0,k1) j-pairs
        const ulonglong2 B = kvrow[p * 3 + 1];   // (k2,v0)
        const ulonglong2 C = kvrow[p * 3 + 2];   // (v1,v2)

        ull d0 = fma2(q00, A.x, fma2(q01, A.y, mul2(q02, B.x)));
        ull d1 = fma2(q10, A.x, fma2(q11, A.y, mul2(q12, B.x)));

        float d0l, d0h, d1l, d1h;
        unpack2(d0, d0l, d0h);
        unpack2(d1, d1l, d1h);
        const ull e0 = pack2(ex2_approx(d0l), ex2_approx(d0h));
        const ull e1 = pack2(ex2_approx(d1l), ex2_approx(d1h));

        s0 = add2(s0, e0);
        a00 = fma2(e0, B.y, a00);
        a01 = fma2(e0, C.x, a01);
        a02 = fma2(e0, C.y, a02);

        s1 = add2(s1, e1);
        a10 = fma2(e1, B.y, a10);
        a11 = fma2(e1, C.x, a11);
        a12 = fma2(e1, C.y, a12);
    }

    // Reduce packed j-halves -> per-query partial (s, a0, a1, a2).
    float lo, hi;
    float4 p0, p1;
    unpack2(s0, lo, hi);  p0.x = lo + hi;
    unpack2(a00, lo, hi); p0.y = lo + hi;
    unpack2(a01, lo, hi); p0.z = lo + hi;
    unpack2(a02, lo, hi); p0.w = lo + hi;
    unpack2(s1, lo, hi);  p1.x = lo + hi;
    unpack2(a10, lo, hi); p1.y = lo + hi;
    unpack2(a11, lo, hi); p1.z = lo + hi;
    unpack2(a12, lo, hi); p1.w = lo + hi;
    pbuf[i0] = p0;
    pbuf[i1] = p1;

    // Cluster barrier: partials visible to peer.
    asm volatile("barrier.cluster.arrive.aligned;" ::: "memory");
    asm volatile("barrier.cluster.wait.aligned;" ::: "memory");

    // Epilogue: finalize queries [z*256, z*256+256).
    const int jq = (int)z * 256 + tid;
    const float4 mine = pbuf[jq];
    float4 theirs;
    {
        u32 laddr = smem_u32(&pbuf[jq]);
        u32 raddr;
        asm("mapa.shared::cluster.u32 %0, %1, %2;" : "=r"(raddr) : "r"(laddr), "r"(z ^ 1u));
        asm("ld.shared::cluster.v4.f32 {%0,%1,%2,%3}, [%4];"
            : "=f"(theirs.x), "=f"(theirs.y), "=f"(theirs.z), "=f"(theirs.w)
            : "r"(raddr));
    }

    const float inv = __fdividef(1.f, mine.x + theirs.x);
    const size_t base = (size_t)bc * SLAB;
    out[base + 0 * NN + jq] = x[base + 0 * NN + jq] + (mine.y + theirs.y) * inv;
    out[base + 1 * NN + jq] = x[base + 1 * NN + jq] + (mine.z + theirs.z) * inv;
    out[base + 2 * NN + jq] = x[base + 2 * NN + jq] + (mine.w + theirs.w) * inv;

    // Keep smem alive until peer finished reading.
    asm volatile("barrier.cluster.arrive.aligned;" ::: "memory");
    asm volatile("barrier.cluster.wait.aligned;" ::: "memory");
}

extern "C" void kernel_launch(void* const* d_in, const int* in_sizes, int n_in,
                              void* d_out, int out_size) {
    const float* x  = (const float*)d_in[0];
    const float* Wq = (const float*)d_in[1];
    const float* Wk = (const float*)d_in[2];
    const float* Wv = (const float*)d_in[3];
    float* out = (float*)d_out;

    dim3 grid1(BB * (CC / TCOUT), UU);
    vn_proj_kernel<<<grid1, 256>>>(x, Wq, Wk, Wv);
    vn_attn_kernel<<<NSLAB * 2, 256>>>(x, out);
}

// round 11
// speedup vs baseline: 1.3576x; 1.3087x over previous
#include <cuda_runtime.h>
#include <cstdint>

// VN_Attention: B=8, C=64, U=3, N=512
// R11 (= R10 resubmit after GPU-broker timeout): ONE fused kernel,
// grid 1024 = 2-CTA cluster per (b,c) slab.
//  Rank z projects x columns n in [z*256, z*256+256): q-half -> smem,
//  k/v j-half -> interleaved j-pair rows (R7 layout). q exchanged via DSMEM.
//  Attention: q=2 queries/thread, f32x2 packed over j-pairs, 128 rows.
//  Partials (s,a0,a1,a2) aliased over kv smem, exchanged via DSMEM.
//  No projection duplication, no global kv round-trip, no second launch.

#define BB 8
#define CC 64
#define UU 3
#define NN 512
#define SLAB (UU * NN)          // 1536 floats
#define SLAB2 (SLAB / 2)        // 768 float2
#define NSLAB (BB * CC)         // 512

typedef unsigned long long ull;
typedef unsigned int u32;

__device__ __forceinline__ float ex2_approx(float x) {
    float r; asm("ex2.approx.ftz.f32 %0, %1;" : "=f"(r) : "f"(x)); return r;
}
__device__ __forceinline__ ull pack2(float lo, float hi) {
    ull r; asm("mov.b64 %0, {%1, %2};" : "=l"(r) : "f"(lo), "f"(hi)); return r;
}
__device__ __forceinline__ void unpack2(ull v, float& lo, float& hi) {
    asm("mov.b64 {%0, %1}, %2;" : "=f"(lo), "=f"(hi) : "l"(v));
}
__device__ __forceinline__ ull fma2(ull a, ull b, ull c) {
    ull d; asm("fma.rn.f32x2 %0, %1, %2, %3;" : "=l"(d) : "l"(a), "l"(b), "l"(c)); return d;
}
__device__ __forceinline__ ull mul2(ull a, ull b) {
    ull d; asm("mul.rn.f32x2 %0, %1, %2;" : "=l"(d) : "l"(a), "l"(b)); return d;
}
__device__ __forceinline__ ull add2(ull a, ull b) {
    ull d; asm("add.rn.f32x2 %0, %1, %2;" : "=l"(d) : "l"(a), "l"(b)); return d;
}
__device__ __forceinline__ u32 smem_u32(const void* p) {
    u32 a;
    asm("{ .reg .u64 t; cvta.to.shared.u64 t, %1; cvt.u32.u64 %0, t; }" : "=r"(a) : "l"(p));
    return a;
}
__device__ __forceinline__ float ld_cluster_f32(u32 laddr, u32 peer) {
    u32 ra; float v;
    asm("mapa.shared::cluster.u32 %0, %1, %2;" : "=r"(ra) : "r"(laddr), "r"(peer));
    asm("ld.shared::cluster.f32 %0, [%1];" : "=f"(v) : "r"(ra));
    return v;
}

#define CLUSTER_BAR() do { \
    asm volatile("barrier.cluster.arrive.aligned;" ::: "memory"); \
    asm volatile("barrier.cluster.wait.aligned;" ::: "memory"); \
} while (0)

__global__ __launch_bounds__(256, 6) __cluster_dims__(2, 1, 1)
void vn_fused_kernel(const float* __restrict__ x,
                     const float* __restrict__ Wq,
                     const float* __restrict__ Wk,
                     const float* __restrict__ Wv,
                     float* __restrict__ out)
{
    __shared__ float wq[CC], wk[CC], wv[CC];
    __shared__ __align__(16) char sbuf[9216];
    ull*    kvU  = reinterpret_cast<ull*>(sbuf);           // [128*6] rows, 6 KB
    float*  qhf  = reinterpret_cast<float*>(sbuf + 6144);  // [3][256], 3 KB
    float4* pbuf = reinterpret_cast<float4*>(sbuf);        // [512] alias, 8 KB

    const int tid = threadIdx.x;
    const int bc = blockIdx.x >> 1;
    const int b = bc >> 6, c = bc & 63;
    u32 z; asm("mov.u32 %0, %%cluster_ctarank;" : "=r"(z));

    if (tid < CC) {
        wq[tid] = Wq[c * CC + tid];
        wk[tid] = Wk[c * CC + tid];
        wv[tid] = Wv[c * CC + tid];
    }
    __syncthreads();

    // ---- Phase 1: project this CTA's half of the slab (384 float2 pos).
    // pos0 = tid covers u=0 (t<128) and u=1 (t>=128); pos1 covers u=2 (t<128).
    const int u0 = tid >> 7, m0 = tid & 127;
    const int off0 = u0 * 256 + (int)z * 128 + m0;
    const bool two = tid < 128;
    const int off1 = 2 * 256 + (int)z * 128 + tid;   // u=2, m=tid

    ull aq0 = 0, ak0 = 0, av0 = 0, aq1 = 0, ak1 = 0, av1 = 0;
    const ull* xb = reinterpret_cast<const ull*>(x) + (size_t)b * CC * SLAB2;
    #pragma unroll 4
    for (int ci = 0; ci < CC; ++ci) {
        const ull wq2 = pack2(wq[ci], wq[ci]);
        const ull wk2 = pack2(wk[ci], wk[ci]);
        const ull wv2 = pack2(wv[ci], wv[ci]);
        const ull xv0 = xb[(size_t)ci * SLAB2 + off0];
        aq0 = fma2(xv0, wq2, aq0);
        ak0 = fma2(xv0, wk2, ak0);
        av0 = fma2(xv0, wv2, av0);
        if (two) {
            const ull xv1 = xb[(size_t)ci * SLAB2 + off1];
            aq1 = fma2(xv1, wq2, aq1);
            ak1 = fma2(xv1, wk2, ak1);
            av1 = fma2(xv1, wv2, av1);
        }
    }

    // Stage: q-half pre-scaled ([u][128] float2); kv interleaved j-pair rows.
    const float qs = 0.125f * 1.44269504088896340736f;  // C^-0.5 * log2(e)
    const ull qs2 = pack2(qs, qs);
    ull* qh2 = reinterpret_cast<ull*>(qhf);
    qh2[u0 * 128 + m0] = mul2(aq0, qs2);
    kvU[m0 * 6 + u0]     = ak0;
    kvU[m0 * 6 + 3 + u0] = av0;
    if (two) {
        qh2[2 * 128 + tid] = mul2(aq1, qs2);
        kvU[tid * 6 + 2]     = ak1;
        kvU[tid * 6 + 3 + 2] = av1;
    }
    __syncthreads();
    CLUSTER_BAR();   // barrier 1: both halves' qh staged & visible

    // ---- Load q for queries i0 = tid (half 0) and i1 = tid+256 (half 1).
    // Local query (half z) and peer query (half z^1) both have local idx tid.
    const float qloc0 = qhf[0 * 256 + tid];
    const float qloc1 = qhf[1 * 256 + tid];
    const float qloc2 = qhf[2 * 256 + tid];
    const u32 zp = z ^ 1u;
    const float qpe0 = ld_cluster_f32(smem_u32(&qhf[0 * 256 + tid]), zp);
    const float qpe1 = ld_cluster_f32(smem_u32(&qhf[1 * 256 + tid]), zp);
    const float qpe2 = ld_cluster_f32(smem_u32(&qhf[2 * 256 + tid]), zp);
    CLUSTER_BAR();   // barrier 2: all q reads done -> qh may be overwritten

    const float qi00 = (z == 0) ? qloc0 : qpe0;   // query i0
    const float qi01 = (z == 0) ? qloc1 : qpe1;
    const float qi02 = (z == 0) ? qloc2 : qpe2;
    const float qi10 = (z == 0) ? qpe0 : qloc0;   // query i1
    const float qi11 = (z == 0) ? qpe1 : qloc1;
    const float qi12 = (z == 0) ? qpe2 : qloc2;

    const ull q00 = pack2(qi00, qi00), q01 = pack2(qi01, qi01), q02 = pack2(qi02, qi02);
    const ull q10 = pack2(qi10, qi10), q11 = pack2(qi11, qi11), q12 = pack2(qi12, qi12);

    // ---- Phase 2: attention over this CTA's 128 j-pair rows.
    ull s0 = 0, a00 = 0, a01 = 0, a02 = 0;
    ull s1 = 0, a10 = 0, a11 = 0, a12 = 0;

    const ulonglong2* kvrow = reinterpret_cast<const ulonglong2*>(kvU);
    #pragma unroll 4
    for (int p = 0; p < 128; ++p) {
        const ulonglong2 A = kvrow[p * 3 + 0];   // (k0,k1) j-pairs
        const ulonglong2 B = kvrow[p * 3 + 1];   // (k2,v0)
        const ulonglong2 C = kvrow[p * 3 + 2];   // (v1,v2)

        ull d0 = fma2(q00, A.x, fma2(q01, A.y, mul2(q02, B.x)));
        ull d1 = fma2(q10, A.x, fma2(q11, A.y, mul2(q12, B.x)));

        float d0l, d0h, d1l, d1h;
        unpack2(d0, d0l, d0h);
        unpack2(d1, d1l, d1h);
        const ull e0 = pack2(ex2_approx(d0l), ex2_approx(d0h));
        const ull e1 = pack2(ex2_approx(d1l), ex2_approx(d1h));

        s0 = add2(s0, e0);
        a00 = fma2(e0, B.y, a00);
        a01 = fma2(e0, C.x, a01);
        a02 = fma2(e0, C.y, a02);

        s1 = add2(s1, e1);
        a10 = fma2(e1, B.y, a10);
        a11 = fma2(e1, C.x, a11);
        a12 = fma2(e1, C.y, a12);
    }

    // Reduce packed j-halves -> per-query partials; alias pbuf over kv/qh.
    float lo, hi;
    float4 p0, p1;
    unpack2(s0, lo, hi);  p0.x = lo + hi;
    unpack2(a00, lo, hi); p0.y = lo + hi;
    unpack2(a01, lo, hi); p0.z = lo + hi;
    unpack2(a02, lo, hi); p0.w = lo + hi;
    unpack2(s1, lo, hi);  p1.x = lo + hi;
    unpack2(a10, lo, hi); p1.y = lo + hi;
    unpack2(a11, lo, hi); p1.z = lo + hi;
    unpack2(a12, lo, hi); p1.w = lo + hi;
    __syncthreads();               // all warps done reading kv
    pbuf[tid] = p0;                // query i0 = tid
    pbuf[tid + 256] = p1;          // query i1 = tid + 256
    CLUSTER_BAR();   // barrier 3: partials visible cluster-wide

    // ---- Epilogue: finalize queries [z*256, z*256+256).
    const int jq = (int)z * 256 + tid;
    const float4 mine = pbuf[jq];
    float4 theirs;
    {
        u32 la = smem_u32(&pbuf[jq]);
        u32 ra;
        asm("mapa.shared::cluster.u32 %0, %1, %2;" : "=r"(ra) : "r"(la), "r"(zp));
        asm("ld.shared::cluster.v4.f32 {%0,%1,%2,%3}, [%4];"
            : "=f"(theirs.x), "=f"(theirs.y), "=f"(theirs.z), "=f"(theirs.w)
            : "r"(ra));
    }

    const float inv = __fdividef(1.f, mine.x + theirs.x);
    const size_t base = (size_t)bc * SLAB;
    out[base + 0 * NN + jq] = x[base + 0 * NN + jq] + (mine.y + theirs.y) * inv;
    out[base + 1 * NN + jq] = x[base + 1 * NN + jq] + (mine.z + theirs.z) * inv;
    out[base + 2 * NN + jq] = x[base + 2 * NN + jq] + (mine.w + theirs.w) * inv;

    CLUSTER_BAR();   // barrier 4: keep smem alive until peer finished reading
}

extern "C" void kernel_launch(void* const* d_in, const int* in_sizes, int n_in,
                              void* d_out, int out_size) {
    const float* x  = (const float*)d_in[0];
    const float* Wq = (const float*)d_in[1];
    const float* Wk = (const float*)d_in[2];
    const float* Wv = (const float*)d_in[3];
    float* out = (float*)d_out;
    vn_fused_kernel<<<NSLAB * 2, 256>>>(x, Wq, Wk, Wv, out);
}